// round 10
// baseline (speedup 1.0000x reference)
#include <cuda_runtime.h>

#define BB 2048
#define LL 256
#define FF 64
#define HH 32
#define G4 256   // 4*F

// Scratch (device globals; no allocation allowed)
__device__ float d_A[BB * G4];     // per-batch input bias
__device__ float d_E[2 * G4];      // per-token embedding projection
__device__ float d_h0[BB * FF];
__device__ float d_c0[BB * FF];
__device__ float d_Y[BB * LL * FF];  // streamed h(t), 134 MB

typedef unsigned long long u64;

__device__ __forceinline__ u64 pack2(float lo, float hi) {
    u64 r; asm("mov.b64 %0, {%1,%2};" : "=l"(r) : "f"(lo), "f"(hi)); return r;
}
__device__ __forceinline__ void fma2(u64 &d, u64 a, u64 b) {
    asm("fma.rn.f32x2 %0, %1, %2, %0;" : "+l"(d) : "l"(a), "l"(b));
}
__device__ __forceinline__ u64 add2(u64 a, u64 b) {
    u64 r; asm("add.rn.f32x2 %0, %1, %2;" : "=l"(r) : "l"(a), "l"(b)); return r;
}
__device__ __forceinline__ float sum2(u64 v) {
    float lo, hi; asm("mov.b64 {%0,%1}, %2;" : "=f"(lo), "=f"(hi) : "l"(v));
    return lo + hi;
}
// MUFU.TANH gates: 1 MUFU each (vs 2 for the expf forms). First CLEAN
// accuracy test of these (R2's failure was the half-dot-product bug).
__device__ __forceinline__ float tanh_mufu(float x) {
    float y; asm("tanh.approx.f32 %0, %1;" : "=f"(y) : "f"(x)); return y;
}
__device__ __forceinline__ float sig_mufu(float x) {
    return fmaf(tanh_mufu(0.5f * x), 0.5f, 0.5f);
}

// ---------------------------------------------------------------------------
// Kernel 1: precompute A[b], E[k], h0[b], c0[b]   (proven; accurate math)
// ---------------------------------------------------------------------------
__global__ void precompute_kernel(
    const float* __restrict__ g,
    const float* __restrict__ W_emb,  const float* __restrict__ b_emb,
    const float* __restrict__ W_g1,   const float* __restrict__ b_g1,
    const float* __restrict__ W_g2,   const float* __restrict__ b_g2,
    const float* __restrict__ W_gh,   const float* __restrict__ b_gh,
    const float* __restrict__ W_gc,   const float* __restrict__ b_gc,
    const float* __restrict__ Wi,     const float* __restrict__ b_lstm)
{
    int b = blockIdx.x;
    int j = threadIdx.x;
    __shared__ float sh_t[HH];
    __shared__ float sh_gv[FF];

    float gb = g[b];
    if (j < HH) sh_t[j] = tanhf(gb * W_g1[j] + b_g1[j]);
    __syncthreads();
    if (j < FF) {
        float acc = b_g2[j];
        #pragma unroll 8
        for (int h = 0; h < HH; h++) acc += sh_t[h] * W_g2[h * FF + j];
        sh_gv[j] = acc;
        d_h0[b * FF + j] = gb * W_gh[j] + b_gh[j];
        d_c0[b * FF + j] = gb * W_gc[j] + b_gc[j];
    }
    __syncthreads();
    float acc = b_lstm[j];
    #pragma unroll 8
    for (int f = 0; f < FF; f++) acc += (b_emb[f] + sh_gv[f]) * Wi[f * G4 + j];
    d_A[b * G4 + j] = acc;

    if (b == 0) {
        float e0 = 0.f, e1 = 0.f;
        #pragma unroll 8
        for (int f = 0; f < FF; f++) {
            float wi = Wi[f * G4 + j];
            e0 += W_emb[f] * wi;
            e1 += W_emb[FF + f] * wi;
        }
        d_E[j] = e0;
        d_E[G4 + j] = e1;
    }
}

// ---------------------------------------------------------------------------
// Kernel 2: LSTM recurrence, G=2 batches per CTA, h streamed to d_Y.
// IDENTICAL structure to the passing R9 kernel; ONLY the gate activation
// implementation changed (expf -> MUFU.TANH).
// ---------------------------------------------------------------------------
__global__ void __launch_bounds__(256, 2) lstm_kernel(
    const int*   __restrict__ s,      // (B, L)
    const float* __restrict__ Wh)     // (64, 256)
{
    int b0   = 2 * blockIdx.x;
    int b1   = b0 + 1;
    int tid  = threadIdx.x;
    int g    = tid >> 2;        // feature 0..63
    int q    = tid & 3;         // gate 0..3 (i,f,g,o)
    int col  = q * FF + g;      // gate column in [0,256)
    int lane = tid & 31;

    __shared__ __align__(16) float sh_h[2][2][FF];   // [batch][parity][feat]
    __shared__ int sh_tok[2][LL];

    // Wh column `col` (shared by both batches), packed f32x2
    u64 w2[32];
    #pragma unroll
    for (int k = 0; k < 32; k++)
        w2[k] = pack2(Wh[(2 * k) * G4 + col], Wh[(2 * k + 1) * G4 + col]);

    float e0 = d_E[col];
    float ed = d_E[G4 + col] - e0;
    float xbase0 = d_A[b0 * G4 + col] + e0;
    float xbase1 = d_A[b1 * G4 + col] + e0;

    sh_tok[0][tid] = s[b0 * LL + tid];
    sh_tok[1][tid] = s[b1 * LL + tid];
    if (tid < FF) {
        sh_h[0][0][tid] = d_h0[b0 * FF + tid];
        sh_h[1][0][tid] = d_h0[b1 * FF + tid];
    }
    float c0 = d_c0[b0 * FF + g];
    float c1 = d_c0[b1 * FF + g];
    float* y0 = d_Y + b0 * LL * FF + g;
    float* y1 = d_Y + b1 * LL * FF + g;
    __syncthreads();

    #pragma unroll 1
    for (int u = 0; u < LL; u++) {
        int p = u & 1;

        // matvecs for both batches, interleaved (independent FMA chains)
        int t0 = (u == 0) ? 0 : sh_tok[0][u - 1];
        int t1 = (u == 0) ? 0 : sh_tok[1][u - 1];
        float x0 = t0 ? (xbase0 + ed) : xbase0;
        float x1 = t1 ? (xbase1 + ed) : xbase1;
        const ulonglong2* hA = (const ulonglong2*)sh_h[0][p];
        const ulonglong2* hB = (const ulonglong2*)sh_h[1][p];
        u64 a0 = pack2(x0, 0.f), a1 = 0ull;
        u64 d0 = pack2(x1, 0.f), d1 = 0ull;
        #pragma unroll
        for (int i = 0; i < 8; i++) {
            ulonglong2 ha = hA[2 * i];
            ulonglong2 hb = hA[2 * i + 1];
            ulonglong2 ga = hB[2 * i];
            ulonglong2 gb = hB[2 * i + 1];
            fma2(a0, ha.x, w2[4 * i + 0]);
            fma2(d0, ga.x, w2[4 * i + 0]);
            fma2(a1, ha.y, w2[4 * i + 1]);
            fma2(d1, ga.y, w2[4 * i + 1]);
            fma2(a0, hb.x, w2[4 * i + 2]);
            fma2(d0, gb.x, w2[4 * i + 2]);
            fma2(a1, hb.y, w2[4 * i + 3]);
            fma2(d1, gb.y, w2[4 * i + 3]);
        }
        float z0 = sum2(add2(a0, a1));
        float z1 = sum2(add2(d0, d1));

        // activate OWN gate (both batches), gather activated 4-tuples
        float act0 = (q == 2) ? tanh_mufu(z0) : sig_mufu(z0);
        float act1 = (q == 2) ? tanh_mufu(z1) : sig_mufu(z1);
        int lb = lane & ~3;
        float ai0 = __shfl_sync(0xffffffffu, act0, lb + 0);
        float ai1 = __shfl_sync(0xffffffffu, act1, lb + 0);
        float af0 = __shfl_sync(0xffffffffu, act0, lb + 1);
        float af1 = __shfl_sync(0xffffffffu, act1, lb + 1);
        float ag0 = __shfl_sync(0xffffffffu, act0, lb + 2);
        float ag1 = __shfl_sync(0xffffffffu, act1, lb + 2);
        float ao0 = __shfl_sync(0xffffffffu, act0, lb + 3);
        float ao1 = __shfl_sync(0xffffffffu, act1, lb + 3);

        c0 = af0 * c0 + ai0 * ag0;
        c1 = af1 * c1 + ai1 * ag1;
        float h0 = ao0 * tanh_mufu(c0);
        float h1 = ao1 * tanh_mufu(c1);
        if (q == 0) {
            sh_h[0][p ^ 1][g] = h0;
            sh_h[1][p ^ 1][g] = h1;
            y0[u * FF] = h0;      // fire-and-forget stream of h(t)
            y1[u * FF] = h1;
        }
        __syncthreads();
    }
}

// ---------------------------------------------------------------------------
// Kernel 3: epilogue — logits, log-softmax, per-batch token-logp sum.
// grid = B, block = 256 (thread t owns timestep t). Accurate math.
// ---------------------------------------------------------------------------
__global__ void __launch_bounds__(256) logit_kernel(
    const int*   __restrict__ s,      // (B, L)
    const float* __restrict__ W_amp,  // (64, 2)
    const float* __restrict__ b_amp,  // (2)
    float* __restrict__ out)          // (B,)
{
    int b = blockIdx.x;
    int t = threadIdx.x;
    int lane = t & 31;
    int warp = t >> 5;

    __shared__ __align__(16) float sw[2 * FF];  // W_amp
    __shared__ float red[8];
    if (t < 2 * FF) sw[t] = W_amp[t];
    __syncthreads();

    const float4* y4 = (const float4*)(d_Y + (b * LL + t) * FF);
    float l0 = b_amp[0], l1 = b_amp[1];
    #pragma unroll
    for (int i = 0; i < 16; i++) {
        float4 y = y4[i];
        int f = 4 * i;
        l0 += y.x * sw[2 * f + 0] + y.y * sw[2 * f + 2]
            + y.z * sw[2 * f + 4] + y.w * sw[2 * f + 6];
        l1 += y.x * sw[2 * f + 1] + y.y * sw[2 * f + 3]
            + y.z * sw[2 * f + 5] + y.w * sw[2 * f + 7];
    }
    int tok = s[b * LL + t];
    float m = fmaxf(l0, l1);
    float lse = m + __logf(__expf(l0 - m) + __expf(l1 - m));
    float lp = (tok ? l1 : l0) - lse;

    #pragma unroll
    for (int o = 16; o > 0; o >>= 1)
        lp += __shfl_down_sync(0xffffffffu, lp, o);
    if (lane == 0) red[warp] = lp;
    __syncthreads();
    if (warp == 0) {
        float v = (lane < 8) ? red[lane] : 0.f;
        #pragma unroll
        for (int o = 4; o > 0; o >>= 1)
            v += __shfl_down_sync(0xffffffffu, v, o);
        if (lane == 0) out[b] = v;
    }
}

// ---------------------------------------------------------------------------
// Launch. Input order:
// 0:s 1:g 2:W_emb 3:b_emb 4:W_g1 5:b_g1 6:W_g2 7:b_g2 8:W_gh 9:b_gh
// 10:W_gc 11:b_gc 12:Wi 13:Wh 14:b_lstm 15:W_amp 16:b_amp
// ---------------------------------------------------------------------------
extern "C" void kernel_launch(void* const* d_in, const int* in_sizes, int n_in,
                              void* d_out, int out_size) {
    const int*   s      = (const int*)  d_in[0];
    const float* g      = (const float*)d_in[1];
    const float* W_emb  = (const float*)d_in[2];
    const float* b_emb  = (const float*)d_in[3];
    const float* W_g1   = (const float*)d_in[4];
    const float* b_g1   = (const float*)d_in[5];
    const float* W_g2   = (const float*)d_in[6];
    const float* b_g2   = (const float*)d_in[7];
    const float* W_gh   = (const float*)d_in[8];
    const float* b_gh   = (const float*)d_in[9];
    const float* W_gc   = (const float*)d_in[10];
    const float* b_gc   = (const float*)d_in[11];
    const float* Wi     = (const float*)d_in[12];
    const float* Wh     = (const float*)d_in[13];
    const float* b_lstm = (const float*)d_in[14];
    const float* W_amp  = (const float*)d_in[15];
    const float* b_amp  = (const float*)d_in[16];
    float* out = (float*)d_out;

    precompute_kernel<<<BB, 256>>>(g, W_emb, b_emb, W_g1, b_g1, W_g2, b_g2,
                                   W_gh, b_gh, W_gc, b_gc, Wi, b_lstm);
    lstm_kernel<<<BB / 2, 256>>>(s, Wh);
    logit_kernel<<<BB, 256>>>(s, W_amp, b_amp, out);
}

// round 11
// speedup vs baseline: 1.6683x; 1.6683x over previous
#include <cuda_runtime.h>

#define BB 2048
#define LL 256
#define FF 64
#define HH 32
#define G4 256   // 4*F

// Scratch (device globals; no allocation allowed)
__device__ float d_A[BB * G4];     // per-batch input bias
__device__ float d_E[2 * G4];      // per-token embedding projection
__device__ float d_h0[BB * FF];
__device__ float d_c0[BB * FF];
__device__ float d_Y[BB * LL * FF];  // streamed h(t), 134 MB

typedef unsigned long long u64;

__device__ __forceinline__ u64 pack2(float lo, float hi) {
    u64 r; asm("mov.b64 %0, {%1,%2};" : "=l"(r) : "f"(lo), "f"(hi)); return r;
}
__device__ __forceinline__ void fma2(u64 &d, u64 a, u64 b) {
    asm("fma.rn.f32x2 %0, %1, %2, %0;" : "+l"(d) : "l"(a), "l"(b));
}
__device__ __forceinline__ u64 add2(u64 a, u64 b) {
    u64 r; asm("add.rn.f32x2 %0, %1, %2;" : "=l"(r) : "l"(a), "l"(b)); return r;
}
__device__ __forceinline__ float sum2(u64 v) {
    float lo, hi; asm("mov.b64 {%0,%1}, %2;" : "=f"(lo), "=f"(hi) : "l"(v));
    return lo + hi;
}
// MUFU.TANH gates — accuracy proven in R10 (rel_err 1.04e-7)
__device__ __forceinline__ float tanh_mufu(float x) {
    float y; asm("tanh.approx.f32 %0, %1;" : "=f"(y) : "f"(x)); return y;
}
__device__ __forceinline__ float sig_mufu(float x) {
    return fmaf(tanh_mufu(0.5f * x), 0.5f, 0.5f);
}

// ---------------------------------------------------------------------------
// Kernel 1: precompute A[b], E[k], h0[b], c0[b]   (proven; accurate math)
// ALSO the clock canary: identical code since R9 (19.6us @ normal clock).
// ---------------------------------------------------------------------------
__global__ void precompute_kernel(
    const float* __restrict__ g,
    const float* __restrict__ W_emb,  const float* __restrict__ b_emb,
    const float* __restrict__ W_g1,   const float* __restrict__ b_g1,
    const float* __restrict__ W_g2,   const float* __restrict__ b_g2,
    const float* __restrict__ W_gh,   const float* __restrict__ b_gh,
    const float* __restrict__ W_gc,   const float* __restrict__ b_gc,
    const float* __restrict__ Wi,     const float* __restrict__ b_lstm)
{
    int b = blockIdx.x;
    int j = threadIdx.x;
    __shared__ float sh_t[HH];
    __shared__ float sh_gv[FF];

    float gb = g[b];
    if (j < HH) sh_t[j] = tanhf(gb * W_g1[j] + b_g1[j]);
    __syncthreads();
    if (j < FF) {
        float acc = b_g2[j];
        #pragma unroll 8
        for (int h = 0; h < HH; h++) acc += sh_t[h] * W_g2[h * FF + j];
        sh_gv[j] = acc;
        d_h0[b * FF + j] = gb * W_gh[j] + b_gh[j];
        d_c0[b * FF + j] = gb * W_gc[j] + b_gc[j];
    }
    __syncthreads();
    float acc = b_lstm[j];
    #pragma unroll 8
    for (int f = 0; f < FF; f++) acc += (b_emb[f] + sh_gv[f]) * Wi[f * G4 + j];
    d_A[b * G4 + j] = acc;

    if (b == 0) {
        float e0 = 0.f, e1 = 0.f;
        #pragma unroll 8
        for (int f = 0; f < FF; f++) {
            float wi = Wi[f * G4 + j];
            e0 += W_emb[f] * wi;
            e1 += W_emb[FF + f] * wi;
        }
        d_E[j] = e0;
        d_E[G4 + j] = e1;
    }
}

// ---------------------------------------------------------------------------
// Kernel 2: LSTM recurrence, G=2 batches per CTA, h streamed to d_Y.
// MUFU.TANH gates. Time loop unrolled x2 so the parity index is
// compile-time constant in each half-step.
// ---------------------------------------------------------------------------
__global__ void __launch_bounds__(256, 2) lstm_kernel(
    const int*   __restrict__ s,      // (B, L)
    const float* __restrict__ Wh)     // (64, 256)
{
    int b0   = 2 * blockIdx.x;
    int b1   = b0 + 1;
    int tid  = threadIdx.x;
    int g    = tid >> 2;        // feature 0..63
    int q    = tid & 3;         // gate 0..3 (i,f,g,o)
    int col  = q * FF + g;      // gate column in [0,256)
    int lane = tid & 31;

    __shared__ __align__(16) float sh_h[2][2][FF];   // [batch][parity][feat]
    __shared__ int sh_tok[2][LL];

    // Wh column `col` (shared by both batches), packed f32x2
    u64 w2[32];
    #pragma unroll
    for (int k = 0; k < 32; k++)
        w2[k] = pack2(Wh[(2 * k) * G4 + col], Wh[(2 * k + 1) * G4 + col]);

    float e0 = d_E[col];
    float ed = d_E[G4 + col] - e0;
    float xbase0 = d_A[b0 * G4 + col] + e0;
    float xbase1 = d_A[b1 * G4 + col] + e0;

    sh_tok[0][tid] = s[b0 * LL + tid];
    sh_tok[1][tid] = s[b1 * LL + tid];
    if (tid < FF) {
        sh_h[0][0][tid] = d_h0[b0 * FF + tid];
        sh_h[1][0][tid] = d_h0[b1 * FF + tid];
    }
    float c0 = d_c0[b0 * FF + g];
    float c1 = d_c0[b1 * FF + g];
    float* y0 = d_Y + b0 * LL * FF + g;
    float* y1 = d_Y + b1 * LL * FF + g;
    __syncthreads();

    #pragma unroll 2
    for (int u = 0; u < LL; u++) {
        int p = u & 1;

        // matvecs for both batches, interleaved (independent FMA chains)
        int t0 = (u == 0) ? 0 : sh_tok[0][u - 1];
        int t1 = (u == 0) ? 0 : sh_tok[1][u - 1];
        float x0 = t0 ? (xbase0 + ed) : xbase0;
        float x1 = t1 ? (xbase1 + ed) : xbase1;
        const ulonglong2* hA = (const ulonglong2*)sh_h[0][p];
        const ulonglong2* hB = (const ulonglong2*)sh_h[1][p];
        u64 a0 = pack2(x0, 0.f), a1 = 0ull;
        u64 d0 = pack2(x1, 0.f), d1 = 0ull;
        #pragma unroll
        for (int i = 0; i < 8; i++) {
            ulonglong2 ha = hA[2 * i];
            ulonglong2 hb = hA[2 * i + 1];
            ulonglong2 ga = hB[2 * i];
            ulonglong2 gb = hB[2 * i + 1];
            fma2(a0, ha.x, w2[4 * i + 0]);
            fma2(d0, ga.x, w2[4 * i + 0]);
            fma2(a1, ha.y, w2[4 * i + 1]);
            fma2(d1, ga.y, w2[4 * i + 1]);
            fma2(a0, hb.x, w2[4 * i + 2]);
            fma2(d0, gb.x, w2[4 * i + 2]);
            fma2(a1, hb.y, w2[4 * i + 3]);
            fma2(d1, gb.y, w2[4 * i + 3]);
        }
        float z0 = sum2(add2(a0, a1));
        float z1 = sum2(add2(d0, d1));

        // activate OWN gate (both batches), gather activated 4-tuples
        float act0 = (q == 2) ? tanh_mufu(z0) : sig_mufu(z0);
        float act1 = (q == 2) ? tanh_mufu(z1) : sig_mufu(z1);
        int lb = lane & ~3;
        float ai0 = __shfl_sync(0xffffffffu, act0, lb + 0);
        float ai1 = __shfl_sync(0xffffffffu, act1, lb + 0);
        float af0 = __shfl_sync(0xffffffffu, act0, lb + 1);
        float af1 = __shfl_sync(0xffffffffu, act1, lb + 1);
        float ag0 = __shfl_sync(0xffffffffu, act0, lb + 2);
        float ag1 = __shfl_sync(0xffffffffu, act1, lb + 2);
        float ao0 = __shfl_sync(0xffffffffu, act0, lb + 3);
        float ao1 = __shfl_sync(0xffffffffu, act1, lb + 3);

        c0 = af0 * c0 + ai0 * ag0;
        c1 = af1 * c1 + ai1 * ag1;
        float h0 = ao0 * tanh_mufu(c0);
        float h1 = ao1 * tanh_mufu(c1);
        if (q == 0) {
            sh_h[0][p ^ 1][g] = h0;
            sh_h[1][p ^ 1][g] = h1;
            y0[u * FF] = h0;      // fire-and-forget stream of h(t)
            y1[u * FF] = h1;
        }
        __syncthreads();
    }
}

// ---------------------------------------------------------------------------
// Kernel 3: epilogue — logits, log-softmax, per-batch token-logp sum.
// grid = B, block = 256 (thread t owns timestep t). Accurate math.
// ---------------------------------------------------------------------------
__global__ void __launch_bounds__(256) logit_kernel(
    const int*   __restrict__ s,      // (B, L)
    const float* __restrict__ W_amp,  // (64, 2)
    const float* __restrict__ b_amp,  // (2)
    float* __restrict__ out)          // (B,)
{
    int b = blockIdx.x;
    int t = threadIdx.x;
    int lane = t & 31;
    int warp = t >> 5;

    __shared__ __align__(16) float sw[2 * FF];  // W_amp
    __shared__ float red[8];
    if (t < 2 * FF) sw[t] = W_amp[t];
    __syncthreads();

    const float4* y4 = (const float4*)(d_Y + (b * LL + t) * FF);
    float l0 = b_amp[0], l1 = b_amp[1];
    #pragma unroll
    for (int i = 0; i < 16; i++) {
        float4 y = y4[i];
        int f = 4 * i;
        l0 += y.x * sw[2 * f + 0] + y.y * sw[2 * f + 2]
            + y.z * sw[2 * f + 4] + y.w * sw[2 * f + 6];
        l1 += y.x * sw[2 * f + 1] + y.y * sw[2 * f + 3]
            + y.z * sw[2 * f + 5] + y.w * sw[2 * f + 7];
    }
    int tok = s[b * LL + t];
    float m = fmaxf(l0, l1);
    float lse = m + __logf(__expf(l0 - m) + __expf(l1 - m));
    float lp = (tok ? l1 : l0) - lse;

    #pragma unroll
    for (int o = 16; o > 0; o >>= 1)
        lp += __shfl_down_sync(0xffffffffu, lp, o);
    if (lane == 0) red[warp] = lp;
    __syncthreads();
    if (warp == 0) {
        float v = (lane < 8) ? red[lane] : 0.f;
        #pragma unroll
        for (int o = 4; o > 0; o >>= 1)
            v += __shfl_down_sync(0xffffffffu, v, o);
        if (lane == 0) out[b] = v;
    }
}

// ---------------------------------------------------------------------------
// Launch. Input order:
// 0:s 1:g 2:W_emb 3:b_emb 4:W_g1 5:b_g1 6:W_g2 7:b_g2 8:W_gh 9:b_gh
// 10:W_gc 11:b_gc 12:Wi 13:Wh 14:b_lstm 15:W_amp 16:b_amp
// ---------------------------------------------------------------------------
extern "C" void kernel_launch(void* const* d_in, const int* in_sizes, int n_in,
                              void* d_out, int out_size) {
    const int*   s      = (const int*)  d_in[0];
    const float* g      = (const float*)d_in[1];
    const float* W_emb  = (const float*)d_in[2];
    const float* b_emb  = (const float*)d_in[3];
    const float* W_g1   = (const float*)d_in[4];
    const float* b_g1   = (const float*)d_in[5];
    const float* W_g2   = (const float*)d_in[6];
    const float* b_g2   = (const float*)d_in[7];
    const float* W_gh   = (const float*)d_in[8];
    const float* b_gh   = (const float*)d_in[9];
    const float* W_gc   = (const float*)d_in[10];
    const float* b_gc   = (const float*)d_in[11];
    const float* Wi     = (const float*)d_in[12];
    const float* Wh     = (const float*)d_in[13];
    const float* b_lstm = (const float*)d_in[14];
    const float* W_amp  = (const float*)d_in[15];
    const float* b_amp  = (const float*)d_in[16];
    float* out = (float*)d_out;

    precompute_kernel<<<BB, 256>>>(g, W_emb, b_emb, W_g1, b_g1, W_g2, b_g2,
                                   W_gh, b_gh, W_gc, b_gc, Wi, b_lstm);
    lstm_kernel<<<BB / 2, 256>>>(s, Wh);
    logit_kernel<<<BB, 256>>>(s, W_amp, b_amp, out);
}